// round 7
// baseline (speedup 1.0000x reference)
#include <cuda_runtime.h>
#include <cstdint>

#define NSEQ 128
#define TB   4096
#define FIN  208
#define HGRU 131
#define HP   132      // activation pitch (g_x)
#define HPW  136      // GRU weight/h pitch: 34 quads, exact 17+17 K-split
#define G3   393      // 3*H
#define G3P  416      // padded 3*H
#define DMLP 255
#define DOUT 17

#define BLK  800      // GRU block: 2 threads per output j
#define NQR  14       // weight quads in registers per thread
#define NQT  3        // weight quads in transposed smem per thread

typedef unsigned long long ull;

// ---- scratch (__device__ globals; zero-initialized at module load;
//      pad regions are never written, so they stay zero across replays) ----
__device__ float g_wpad[G3 * HPW];       // W_hh padded [393][136]
__device__ float g_gi[NSEQ * G3];
__device__ float g_x[NSEQ * HP];         // GRU outputs, pitch 132
__device__ float g_wiht[FIN * G3P];      // W_ih^T [208][416]
__device__ float g_bihp[G3P];
__device__ float g_wmt[5][256 * 256];    // W1..W5 transposed [k][c]
__device__ float g_bmp[5][256];
__device__ float g_w6t[256 * 32];        // W6^T [k][c]
__device__ float g_b6p[32];

// ---- prep: coalesced reads, scattered writes ----
__global__ void prep_kernel(const float* __restrict__ Whh,
                            const float* __restrict__ Wih,
                            const float* __restrict__ bih,
                            const float* __restrict__ W1, const float* __restrict__ b1,
                            const float* __restrict__ W2, const float* __restrict__ b2,
                            const float* __restrict__ W3, const float* __restrict__ b3,
                            const float* __restrict__ W4, const float* __restrict__ b4,
                            const float* __restrict__ W5, const float* __restrict__ b5,
                            const float* __restrict__ W6, const float* __restrict__ b6)
{
    int idx = blockIdx.x * blockDim.x + threadIdx.x;

    if (idx < G3 * HGRU) {                         // W_hh pad (row-major copy)
        int j = idx / HGRU, k = idx - j * HGRU;
        g_wpad[j * HPW + k] = Whh[idx];
        return;
    }
    idx -= G3 * HGRU;
    if (idx < G3 * FIN) {                          // W_ih transpose
        int j = idx / FIN, k = idx - j * FIN;
        g_wiht[k * G3P + j] = Wih[idx];
        return;
    }
    idx -= G3 * FIN;
    if (idx < G3) { g_bihp[idx] = bih[idx]; return; }
    idx -= G3;
    if (idx < DMLP * HGRU) {                       // W1 transpose
        int c = idx / HGRU, k = idx - c * HGRU;
        g_wmt[0][k * 256 + c] = W1[idx];
        return;
    }
    idx -= DMLP * HGRU;
    if (idx < 4 * DMLP * DMLP) {                   // W2..W5 transpose
        int l = idx / (DMLP * DMLP);
        int r = idx - l * (DMLP * DMLP);
        int c = r / DMLP, k = r - c * DMLP;
        const float* W = (l == 0) ? W2 : (l == 1) ? W3 : (l == 2) ? W4 : W5;
        g_wmt[l + 1][k * 256 + c] = W[r];
        return;
    }
    idx -= 4 * DMLP * DMLP;
    if (idx < 5 * DMLP) {                          // b1..b5
        int l = idx / DMLP, c = idx - l * DMLP;
        const float* B = (l == 0) ? b1 : (l == 1) ? b2 : (l == 2) ? b3
                        : (l == 3) ? b4 : b5;
        g_bmp[l][c] = B[c];
        return;
    }
    idx -= 5 * DMLP;
    if (idx < DOUT * DMLP) {                       // W6 transpose
        int c = idx / DMLP, k = idx - c * DMLP;
        g_w6t[k * 32 + c] = W6[idx];
        return;
    }
    idx -= DOUT * DMLP;
    if (idx < DOUT) g_b6p[idx] = b6[idx];
}

// ---- gi projection ----
__global__ __launch_bounds__(G3P) void gi_kernel(const float* __restrict__ hist)
{
    __shared__ float2 xs[FIN];
    const int j = threadIdx.x;
    const int r0 = blockIdx.x * 2;

    const float* h0 = hist + ((size_t)r0 * TB + (TB - 1)) * FIN;
    const float* h1 = hist + ((size_t)(r0 + 1) * TB + (TB - 1)) * FIN;
    for (int k = j; k < FIN; k += G3P) xs[k] = make_float2(h0[k], h1[k]);
    __syncthreads();

    float bv = g_bihp[j];
    float a0 = bv, a1 = bv;
#pragma unroll 16
    for (int k = 0; k < FIN; k++) {
        float w = g_wiht[k * G3P + j];
        float2 x = xs[k];
        a0 = fmaf(x.x, w, a0);
        a1 = fmaf(x.y, w, a1);
    }
    if (j < G3) {
        g_gi[r0 * G3 + j]       = a0;
        g_gi[(r0 + 1) * G3 + j] = a1;
    }
}

// ---- fused 6-layer MLP: 64 col-groups x 4-way K-split, float4 weights ----
__global__ __launch_bounds__(256) void mlp_kernel(float* __restrict__ out)
{
    __shared__ float2 xbuf[256];
    __shared__ float4 red[4][64][2];
    const int tid = threadIdx.x;
    const int cg = tid & 63;        // column group: cols 4cg..4cg+3
    const int ks = tid >> 6;        // K-split 0..3: k in [64ks, 64ks+64)
    const int r0 = blockIdx.x * 2;
    const int kbase = ks * 64;

    float2 v = make_float2(0.f, 0.f);
    if (tid < HGRU) v = make_float2(g_x[r0 * HP + tid], g_x[(r0 + 1) * HP + tid]);
    xbuf[tid] = v;                  // cols 131..255 zero
    __syncthreads();

#pragma unroll
    for (int l = 0; l < 5; l++) {
        const float4* wt4 = reinterpret_cast<const float4*>(g_wmt[l]);
        float4 a0 = make_float4(0.f, 0.f, 0.f, 0.f);
        float4 a1 = a0;
#pragma unroll 8
        for (int kk = 0; kk < 64; kk++) {
            int k = kbase + kk;
            float4 w = wt4[k * 64 + cg];
            float2 x = xbuf[k];
            a0.x = fmaf(x.x, w.x, a0.x); a0.y = fmaf(x.x, w.y, a0.y);
            a0.z = fmaf(x.x, w.z, a0.z); a0.w = fmaf(x.x, w.w, a0.w);
            a1.x = fmaf(x.y, w.x, a1.x); a1.y = fmaf(x.y, w.y, a1.y);
            a1.z = fmaf(x.y, w.z, a1.z); a1.w = fmaf(x.y, w.w, a1.w);
        }
        red[ks][cg][0] = a0;
        red[ks][cg][1] = a1;
        __syncthreads();            // also: all xbuf reads done
        if (ks == 0) {
            float4 s0 = red[0][cg][0], s1 = red[0][cg][1];
#pragma unroll
            for (int q = 1; q < 4; q++) {
                float4 t0 = red[q][cg][0], t1 = red[q][cg][1];
                s0.x += t0.x; s0.y += t0.y; s0.z += t0.z; s0.w += t0.w;
                s1.x += t1.x; s1.y += t1.y; s1.z += t1.z; s1.w += t1.w;
            }
            float4 b = reinterpret_cast<const float4*>(g_bmp[l])[cg];
            xbuf[4 * cg + 0] = make_float2(fmaxf(s0.x + b.x, 0.f), fmaxf(s1.x + b.x, 0.f));
            xbuf[4 * cg + 1] = make_float2(fmaxf(s0.y + b.y, 0.f), fmaxf(s1.y + b.y, 0.f));
            xbuf[4 * cg + 2] = make_float2(fmaxf(s0.z + b.z, 0.f), fmaxf(s1.z + b.z, 0.f));
            xbuf[4 * cg + 3] = make_float2(fmaxf(s0.w + b.w, 0.f), fmaxf(s1.w + b.w, 0.f));
        }
        __syncthreads();
    }

    // layer 6: 17 outputs (weights padded to 32 cols)
    {
        const float4* w6 = reinterpret_cast<const float4*>(g_w6t);
        float4 a0 = make_float4(0.f, 0.f, 0.f, 0.f);
        float4 a1 = a0;
        if (cg < 8) {
#pragma unroll 8
            for (int kk = 0; kk < 64; kk++) {
                int k = kbase + kk;
                float4 w = w6[k * 8 + cg];
                float2 x = xbuf[k];
                a0.x = fmaf(x.x, w.x, a0.x); a0.y = fmaf(x.x, w.y, a0.y);
                a0.z = fmaf(x.x, w.z, a0.z); a0.w = fmaf(x.x, w.w, a0.w);
                a1.x = fmaf(x.y, w.x, a1.x); a1.y = fmaf(x.y, w.y, a1.y);
                a1.z = fmaf(x.y, w.z, a1.z); a1.w = fmaf(x.y, w.w, a1.w);
            }
        }
        red[ks][cg][0] = a0;
        red[ks][cg][1] = a1;
        __syncthreads();
        if (ks == 0 && cg < 5) {
            float4 s0 = red[0][cg][0], s1 = red[0][cg][1];
#pragma unroll
            for (int q = 1; q < 4; q++) {
                float4 t0 = red[q][cg][0], t1 = red[q][cg][1];
                s0.x += t0.x; s0.y += t0.y; s0.z += t0.z; s0.w += t0.w;
                s1.x += t1.x; s1.y += t1.y; s1.z += t1.z; s1.w += t1.w;
            }
            float4 b = reinterpret_cast<const float4*>(g_b6p)[cg];
            float o0[4] = {s0.x + b.x, s0.y + b.y, s0.z + b.z, s0.w + b.w};
            float o1[4] = {s1.x + b.x, s1.y + b.y, s1.z + b.z, s1.w + b.w};
#pragma unroll
            for (int i = 0; i < 4; i++) {
                int c = 4 * cg + i;
                if (c < DOUT) {
                    out[r0 * DOUT + c]       = o0[i];
                    out[(r0 + 1) * DOUT + c] = o1[i];
                }
            }
        }
    }
}

// ---- GRU recurrence: K-split=2 (unchanged; profiled this round) ----
__device__ __forceinline__ float fast_sigmoid(float x) {
    return 1.f / (1.f + __expf(-x));
}
__device__ __forceinline__ float fast_tanh(float x) {
    float e = __expf(-2.f * x);
    return (1.f - e) / (1.f + e);
}
__device__ __forceinline__ void fma2(ull& acc, ull h, ull w) {
    asm("fma.rn.f32x2 %0, %1, %2, %0;" : "+l"(acc) : "l"(h), "l"(w));
}

__global__ __launch_bounds__(BLK, 1) void gru_kernel(const float* __restrict__ b_hh)
{
    __shared__ __align__(16) float h_sh[HPW];
    __shared__ float gh_sh[G3];
    __shared__ float gi_sh[G3];
    __shared__ ulonglong2 tailq[NQT][BLK];

    const int tid = threadIdx.x;
    const int j = tid >> 1;
    const int s = tid & 1;
    const bool jv = (j < G3);

    ulonglong2 wq[NQR];
    {
        const ulonglong2* wr = reinterpret_cast<const ulonglong2*>(
            g_wpad + (jv ? j : 0) * HPW) + s * 17;
#pragma unroll
        for (int q = 0; q < NQR; q++) {
            ulonglong2 v = wr[q];
            if (!jv) { v.x = 0ULL; v.y = 0ULL; }
            wq[q] = v;
        }
#pragma unroll
        for (int t = 0; t < NQT; t++) {
            ulonglong2 v = wr[NQR + t];
            if (!jv) { v.x = 0ULL; v.y = 0ULL; }
            tailq[t][tid] = v;
        }
    }

    float bh0 = 0.f, bh1 = 0.f, bh2 = 0.f;
    if (tid < HGRU) {
        bh0 = b_hh[tid];
        bh1 = b_hh[tid + HGRU];
        bh2 = b_hh[tid + 2 * HGRU];
    }
    if (tid < HPW) h_sh[tid] = 0.f;

    float gi_v = (tid < G3) ? g_gi[tid] : 0.f;
    __syncthreads();

    const ulonglong2* hv2 = reinterpret_cast<const ulonglong2*>(h_sh) + s * 17;

    for (int n = 0; n < NSEQ; n++) {
        float gi_cur = gi_v;
        if (tid < G3 && n + 1 < NSEQ) gi_v = __ldg(g_gi + (n + 1) * G3 + tid);

        {
            ull acc0 = 0ULL, acc1 = 0ULL;
#pragma unroll
            for (int q = 0; q < NQR; q++) {
                ulonglong2 h = hv2[q];
                fma2(acc0, h.x, wq[q].x);
                fma2(acc1, h.y, wq[q].y);
            }
#pragma unroll
            for (int t = 0; t < NQT; t++) {
                ulonglong2 h = hv2[NQR + t];
                ulonglong2 w = tailq[t][tid];
                fma2(acc0, h.x, w.x);
                fma2(acc1, h.y, w.y);
            }
            float a0, a1, a2, a3;
            asm("mov.b64 {%0, %1}, %2;" : "=f"(a0), "=f"(a1) : "l"(acc0));
            asm("mov.b64 {%0, %1}, %2;" : "=f"(a2), "=f"(a3) : "l"(acc1));
            float p = (a0 + a2) + (a1 + a3);
            p += __shfl_xor_sync(0xffffffffu, p, 1);
            if (jv && s == 0) gh_sh[j] = p;
            if (tid < G3) gi_sh[tid] = gi_cur;
        }
        __syncthreads();

        if (tid < HGRU) {
            float ir = gi_sh[tid];
            float iz = gi_sh[tid + HGRU];
            float in_ = gi_sh[tid + 2 * HGRU];
            float hr = gh_sh[tid] + bh0;
            float hz = gh_sh[tid + HGRU] + bh1;
            float hn = gh_sh[tid + 2 * HGRU] + bh2;
            float r  = fast_sigmoid(ir + hr);
            float z  = fast_sigmoid(iz + hz);
            float nn = fast_tanh(in_ + r * hn);
            float hp = h_sh[tid];
            float hnew = nn + z * (hp - nn);
            h_sh[tid] = hnew;
            g_x[n * HP + tid] = hnew;
        }
        __syncthreads();
    }
}

// ---- dummy: shifts gru_kernel into profiled launch slot #4 ----
__global__ void dummy_kernel() {}

extern "C" void kernel_launch(void* const* d_in, const int* in_sizes, int n_in,
                              void* d_out, int out_size)
{
    const float* history = (const float*)d_in[0];
    const float* W_ih = (const float*)d_in[1];
    const float* W_hh = (const float*)d_in[2];
    const float* b_ih = (const float*)d_in[3];
    const float* b_hh = (const float*)d_in[4];
    const float* W1 = (const float*)d_in[5];  const float* b1 = (const float*)d_in[6];
    const float* W2 = (const float*)d_in[7];  const float* b2 = (const float*)d_in[8];
    const float* W3 = (const float*)d_in[9];  const float* b3 = (const float*)d_in[10];
    const float* W4 = (const float*)d_in[11]; const float* b4 = (const float*)d_in[12];
    const float* W5 = (const float*)d_in[13]; const float* b5 = (const float*)d_in[14];
    const float* W6 = (const float*)d_in[15]; const float* b6 = (const float*)d_in[16];
    float* out = (float*)d_out;

    const int prep_total = G3 * HGRU + G3 * FIN + G3 + DMLP * HGRU
                         + 4 * DMLP * DMLP + 5 * DMLP + DOUT * DMLP + DOUT;

    dummy_kernel<<<1, 32>>>();                                      // launch 1
    prep_kernel<<<(prep_total + 511) / 512, 512>>>(                 // launch 2
        W_hh, W_ih, b_ih, W1, b1, W2, b2, W3, b3, W4, b4, W5, b5, W6, b6);
    gi_kernel<<<NSEQ / 2, G3P>>>(history);                          // launch 3
    gru_kernel<<<1, BLK>>>(b_hh);                                   // launch 4 (profiled)
    mlp_kernel<<<NSEQ / 2, 256>>>(out);                             // launch 5
}

// round 8
// speedup vs baseline: 1.1924x; 1.1924x over previous
#include <cuda_runtime.h>
#include <cstdint>

#define NSEQ 128
#define TB   4096
#define FIN  208
#define HGRU 131
#define HP   132      // activation pitch (g_x)
#define HPW  136      // W_hh row pitch (34 quads; cols 131..135 zero)
#define G3   393      // 3*H
#define G3P  416      // padded 3*H
#define DMLP 255
#define DOUT 17

#define NREGP 52      // GRU weight pairs in registers (104 floats)
#define NTAIL 14      // GRU weight pairs in transposed smem (28 floats)
// NREGP+NTAIL = 66 pairs = 132 floats (cols 0..131)

typedef unsigned long long ull;

// ---- scratch (__device__ globals; zero-initialized; pads never written) ----
__device__ float g_wpad[G3 * HPW];       // W_hh padded [393][136]
__device__ float g_gi[NSEQ * G3];
__device__ float g_x[NSEQ * HP];         // GRU outputs, pitch 132
__device__ float g_wiht[FIN * G3P];      // W_ih^T [208][416]
__device__ float g_bihp[G3P];
__device__ float g_wmt[5][256 * 256];    // W1..W5 transposed [k][c]
__device__ float g_bmp[5][256];
__device__ float g_w6t[256 * 32];        // W6^T [k][c]
__device__ float g_b6p[32];

// ---- prep: coalesced reads, scattered writes ----
__global__ void prep_kernel(const float* __restrict__ Whh,
                            const float* __restrict__ Wih,
                            const float* __restrict__ bih,
                            const float* __restrict__ W1, const float* __restrict__ b1,
                            const float* __restrict__ W2, const float* __restrict__ b2,
                            const float* __restrict__ W3, const float* __restrict__ b3,
                            const float* __restrict__ W4, const float* __restrict__ b4,
                            const float* __restrict__ W5, const float* __restrict__ b5,
                            const float* __restrict__ W6, const float* __restrict__ b6)
{
    int idx = blockIdx.x * blockDim.x + threadIdx.x;

    if (idx < G3 * HGRU) {
        int j = idx / HGRU, k = idx - j * HGRU;
        g_wpad[j * HPW + k] = Whh[idx];
        return;
    }
    idx -= G3 * HGRU;
    if (idx < G3 * FIN) {
        int j = idx / FIN, k = idx - j * FIN;
        g_wiht[k * G3P + j] = Wih[idx];
        return;
    }
    idx -= G3 * FIN;
    if (idx < G3) { g_bihp[idx] = bih[idx]; return; }
    idx -= G3;
    if (idx < DMLP * HGRU) {
        int c = idx / HGRU, k = idx - c * HGRU;
        g_wmt[0][k * 256 + c] = W1[idx];
        return;
    }
    idx -= DMLP * HGRU;
    if (idx < 4 * DMLP * DMLP) {
        int l = idx / (DMLP * DMLP);
        int r = idx - l * (DMLP * DMLP);
        int c = r / DMLP, k = r - c * DMLP;
        const float* W = (l == 0) ? W2 : (l == 1) ? W3 : (l == 2) ? W4 : W5;
        g_wmt[l + 1][k * 256 + c] = W[r];
        return;
    }
    idx -= 4 * DMLP * DMLP;
    if (idx < 5 * DMLP) {
        int l = idx / DMLP, c = idx - l * DMLP;
        const float* B = (l == 0) ? b1 : (l == 1) ? b2 : (l == 2) ? b3
                        : (l == 3) ? b4 : b5;
        g_bmp[l][c] = B[c];
        return;
    }
    idx -= 5 * DMLP;
    if (idx < DOUT * DMLP) {
        int c = idx / DMLP, k = idx - c * DMLP;
        g_w6t[k * 32 + c] = W6[idx];
        return;
    }
    idx -= DOUT * DMLP;
    if (idx < DOUT) g_b6p[idx] = b6[idx];
}

// ---- gi projection ----
__global__ __launch_bounds__(G3P) void gi_kernel(const float* __restrict__ hist)
{
    __shared__ float2 xs[FIN];
    const int j = threadIdx.x;
    const int r0 = blockIdx.x * 2;

    const float* h0 = hist + ((size_t)r0 * TB + (TB - 1)) * FIN;
    const float* h1 = hist + ((size_t)(r0 + 1) * TB + (TB - 1)) * FIN;
    for (int k = j; k < FIN; k += G3P) xs[k] = make_float2(h0[k], h1[k]);
    __syncthreads();

    float bv = g_bihp[j];
    float a0 = bv, a1 = bv;
#pragma unroll 16
    for (int k = 0; k < FIN; k++) {
        float w = g_wiht[k * G3P + j];
        float2 x = xs[k];
        a0 = fmaf(x.x, w, a0);
        a1 = fmaf(x.y, w, a1);
    }
    if (j < G3) {
        g_gi[r0 * G3 + j]       = a0;
        g_gi[(r0 + 1) * G3 + j] = a1;
    }
}

// ---- fused 6-layer MLP: 64 col-groups x 4-way K-split, float4 weights ----
__global__ __launch_bounds__(256) void mlp_kernel(float* __restrict__ out)
{
    __shared__ float2 xbuf[256];
    __shared__ float4 red[4][64][2];
    const int tid = threadIdx.x;
    const int cg = tid & 63;
    const int ks = tid >> 6;
    const int r0 = blockIdx.x * 2;
    const int kbase = ks * 64;

    float2 v = make_float2(0.f, 0.f);
    if (tid < HGRU) v = make_float2(g_x[r0 * HP + tid], g_x[(r0 + 1) * HP + tid]);
    xbuf[tid] = v;
    __syncthreads();

#pragma unroll
    for (int l = 0; l < 5; l++) {
        const float4* wt4 = reinterpret_cast<const float4*>(g_wmt[l]);
        float4 a0 = make_float4(0.f, 0.f, 0.f, 0.f);
        float4 a1 = a0;
#pragma unroll 8
        for (int kk = 0; kk < 64; kk++) {
            int k = kbase + kk;
            float4 w = wt4[k * 64 + cg];
            float2 x = xbuf[k];
            a0.x = fmaf(x.x, w.x, a0.x); a0.y = fmaf(x.x, w.y, a0.y);
            a0.z = fmaf(x.x, w.z, a0.z); a0.w = fmaf(x.x, w.w, a0.w);
            a1.x = fmaf(x.y, w.x, a1.x); a1.y = fmaf(x.y, w.y, a1.y);
            a1.z = fmaf(x.y, w.z, a1.z); a1.w = fmaf(x.y, w.w, a1.w);
        }
        red[ks][cg][0] = a0;
        red[ks][cg][1] = a1;
        __syncthreads();
        if (ks == 0) {
            float4 s0 = red[0][cg][0], s1 = red[0][cg][1];
#pragma unroll
            for (int q = 1; q < 4; q++) {
                float4 t0 = red[q][cg][0], t1 = red[q][cg][1];
                s0.x += t0.x; s0.y += t0.y; s0.z += t0.z; s0.w += t0.w;
                s1.x += t1.x; s1.y += t1.y; s1.z += t1.z; s1.w += t1.w;
            }
            float4 b = reinterpret_cast<const float4*>(g_bmp[l])[cg];
            xbuf[4 * cg + 0] = make_float2(fmaxf(s0.x + b.x, 0.f), fmaxf(s1.x + b.x, 0.f));
            xbuf[4 * cg + 1] = make_float2(fmaxf(s0.y + b.y, 0.f), fmaxf(s1.y + b.y, 0.f));
            xbuf[4 * cg + 2] = make_float2(fmaxf(s0.z + b.z, 0.f), fmaxf(s1.z + b.z, 0.f));
            xbuf[4 * cg + 3] = make_float2(fmaxf(s0.w + b.w, 0.f), fmaxf(s1.w + b.w, 0.f));
        }
        __syncthreads();
    }

    {
        const float4* w6 = reinterpret_cast<const float4*>(g_w6t);
        float4 a0 = make_float4(0.f, 0.f, 0.f, 0.f);
        float4 a1 = a0;
        if (cg < 8) {
#pragma unroll 8
            for (int kk = 0; kk < 64; kk++) {
                int k = kbase + kk;
                float4 w = w6[k * 8 + cg];
                float2 x = xbuf[k];
                a0.x = fmaf(x.x, w.x, a0.x); a0.y = fmaf(x.x, w.y, a0.y);
                a0.z = fmaf(x.x, w.z, a0.z); a0.w = fmaf(x.x, w.w, a0.w);
                a1.x = fmaf(x.y, w.x, a1.x); a1.y = fmaf(x.y, w.y, a1.y);
                a1.z = fmaf(x.y, w.z, a1.z); a1.w = fmaf(x.y, w.w, a1.w);
            }
        }
        red[ks][cg][0] = a0;
        red[ks][cg][1] = a1;
        __syncthreads();
        if (ks == 0 && cg < 5) {
            float4 s0 = red[0][cg][0], s1 = red[0][cg][1];
#pragma unroll
            for (int q = 1; q < 4; q++) {
                float4 t0 = red[q][cg][0], t1 = red[q][cg][1];
                s0.x += t0.x; s0.y += t0.y; s0.z += t0.z; s0.w += t0.w;
                s1.x += t1.x; s1.y += t1.y; s1.z += t1.z; s1.w += t1.w;
            }
            float4 b = reinterpret_cast<const float4*>(g_b6p)[cg];
            float o0[4] = {s0.x + b.x, s0.y + b.y, s0.z + b.z, s0.w + b.w};
            float o1[4] = {s1.x + b.x, s1.y + b.y, s1.z + b.z, s1.w + b.w};
#pragma unroll
            for (int i = 0; i < 4; i++) {
                int c = 4 * cg + i;
                if (c < DOUT) {
                    out[r0 * DOUT + c]       = o0[i];
                    out[(r0 + 1) * DOUT + c] = o1[i];
                }
            }
        }
    }
}

// ---- GRU recurrence: R4 config (1 thread/output, 416 thr), 52 reg pairs ----
__device__ __forceinline__ float fast_sigmoid(float x) {
    return 1.f / (1.f + __expf(-x));
}
__device__ __forceinline__ float fast_tanh(float x) {
    float e = __expf(-2.f * x);
    return (1.f - e) / (1.f + e);
}
__device__ __forceinline__ void fma2(ull& acc, ull h, ull w) {
    asm("fma.rn.f32x2 %0, %1, %2, %0;" : "+l"(acc) : "l"(h), "l"(w));
}

__global__ __launch_bounds__(G3P, 1) void gru_kernel(const float* __restrict__ b_hh)
{
    __shared__ __align__(16) float h_sh[HP];     // 33 quads
    __shared__ float gh_sh[G3];
    __shared__ float gi_sh[G3];
    __shared__ ull tail_w[NTAIL][G3P];           // transposed tail pairs

    const int j = threadIdx.x;

    ull w2[NREGP];
    float bj = 0.f;
    if (j < G3) {
        const ull* wr = reinterpret_cast<const ull*>(g_wpad + j * HPW);
#pragma unroll
        for (int i = 0; i < NREGP; i++) w2[i] = wr[i];
#pragma unroll
        for (int t = 0; t < NTAIL; t++) tail_w[t][j] = wr[NREGP + t];
        bj = b_hh[j];
    }
    if (j < HP) h_sh[j] = 0.f;

    float gi_v = (j < G3) ? g_gi[j] : 0.f;
    __syncthreads();

    const ulonglong2* hv2 = reinterpret_cast<const ulonglong2*>(h_sh);

    for (int n = 0; n < NSEQ; n++) {
        float gi_cur = gi_v;
        if (j < G3 && n + 1 < NSEQ) gi_v = __ldg(g_gi + (n + 1) * G3 + j);

        if (j < G3) {
            ull acc0, acc1 = 0ULL;
            asm("mov.b64 %0, {%1, %2};" : "=l"(acc0) : "f"(bj), "f"(0.f));
            // register part: pairs 0..51 (floats 0..103, quads 0..25)
#pragma unroll
            for (int i = 0; i < NREGP / 2; i++) {
                ulonglong2 h = hv2[i];
                fma2(acc0, h.x, w2[2 * i]);
                fma2(acc1, h.y, w2[2 * i + 1]);
            }
            // smem tail: pairs 52..65 (floats 104..131, quads 26..32)
#pragma unroll
            for (int t = 0; t < NTAIL / 2; t++) {
                ulonglong2 h = hv2[NREGP / 2 + t];
                fma2(acc0, h.x, tail_w[2 * t][j]);
                fma2(acc1, h.y, tail_w[2 * t + 1][j]);
            }
            float a0, a1, a2, a3;
            asm("mov.b64 {%0, %1}, %2;" : "=f"(a0), "=f"(a1) : "l"(acc0));
            asm("mov.b64 {%0, %1}, %2;" : "=f"(a2), "=f"(a3) : "l"(acc1));
            gh_sh[j] = (a0 + a2) + (a1 + a3);
            gi_sh[j] = gi_cur;
        }
        __syncthreads();

        if (j < HGRU) {
            float ir = gi_sh[j], iz = gi_sh[j + HGRU], in_ = gi_sh[j + 2 * HGRU];
            float hr = gh_sh[j], hz = gh_sh[j + HGRU], hn = gh_sh[j + 2 * HGRU];
            float r  = fast_sigmoid(ir + hr);
            float z  = fast_sigmoid(iz + hz);
            float nn = fast_tanh(in_ + r * hn);
            float hp = h_sh[j];
            float hnew = nn + z * (hp - nn);
            h_sh[j] = hnew;
            g_x[n * HP + j] = hnew;
        }
        __syncthreads();
    }
}

extern "C" void kernel_launch(void* const* d_in, const int* in_sizes, int n_in,
                              void* d_out, int out_size)
{
    const float* history = (const float*)d_in[0];
    const float* W_ih = (const float*)d_in[1];
    const float* W_hh = (const float*)d_in[2];
    const float* b_ih = (const float*)d_in[3];
    const float* b_hh = (const float*)d_in[4];
    const float* W1 = (const float*)d_in[5];  const float* b1 = (const float*)d_in[6];
    const float* W2 = (const float*)d_in[7];  const float* b2 = (const float*)d_in[8];
    const float* W3 = (const float*)d_in[9];  const float* b3 = (const float*)d_in[10];
    const float* W4 = (const float*)d_in[11]; const float* b4 = (const float*)d_in[12];
    const float* W5 = (const float*)d_in[13]; const float* b5 = (const float*)d_in[14];
    const float* W6 = (const float*)d_in[15]; const float* b6 = (const float*)d_in[16];
    float* out = (float*)d_out;

    const int prep_total = G3 * HGRU + G3 * FIN + G3 + DMLP * HGRU
                         + 4 * DMLP * DMLP + 5 * DMLP + DOUT * DMLP + DOUT;

    prep_kernel<<<(prep_total + 511) / 512, 512>>>(                 // launch 1
        W_hh, W_ih, b_ih, W1, b1, W2, b2, W3, b3, W4, b4, W5, b5, W6, b6);
    gi_kernel<<<NSEQ / 2, G3P>>>(history);                          // launch 2
    gru_kernel<<<1, G3P>>>(b_hh);                                   // launch 3
    mlp_kernel<<<NSEQ / 2, 256>>>(out);                             // launch 4 (profiled)
}

// round 9
// speedup vs baseline: 1.3278x; 1.1135x over previous
#include <cuda_runtime.h>
#include <cstdint>

#define NSEQ 128
#define TB   4096
#define FIN  208
#define HGRU 131
#define HP   132      // activation pitch (g_x)
#define HPW  136      // W_hh row pitch (34 quads; cols 131..135 zero)
#define G3   393      // 3*H
#define G3P  416      // padded 3*H
#define DMLP 255
#define DOUT 17

#define NREGP 48      // GRU weight pairs in registers (96 floats = 24 quads)
#define NTAIL 18      // GRU weight pairs in transposed smem (9 quads)

typedef unsigned long long ull;

// ---- scratch (__device__ globals; zero-initialized; pads never written) ----
__device__ float g_wpad[G3 * HPW];       // W_hh padded [393][136]
__device__ float g_gi[NSEQ * G3];
__device__ float g_x[NSEQ * HP];         // GRU outputs, pitch 132
__device__ float g_wiht[FIN * G3P];      // W_ih^T [208][416]
__device__ float g_bihp[G3P];
__device__ float g_wmt[5][256 * 256];    // W1..W5 transposed [k][c]
__device__ float g_bmp[5][256];
__device__ float g_w6t[256 * 32];        // W6^T [k][c]
__device__ float g_b6p[32];

// ---- prep: coalesced reads, scattered writes ----
__global__ void prep_kernel(const float* __restrict__ Whh,
                            const float* __restrict__ Wih,
                            const float* __restrict__ bih,
                            const float* __restrict__ W1, const float* __restrict__ b1,
                            const float* __restrict__ W2, const float* __restrict__ b2,
                            const float* __restrict__ W3, const float* __restrict__ b3,
                            const float* __restrict__ W4, const float* __restrict__ b4,
                            const float* __restrict__ W5, const float* __restrict__ b5,
                            const float* __restrict__ W6, const float* __restrict__ b6)
{
    int idx = blockIdx.x * blockDim.x + threadIdx.x;

    if (idx < G3 * HGRU) {
        int j = idx / HGRU, k = idx - j * HGRU;
        g_wpad[j * HPW + k] = Whh[idx];
        return;
    }
    idx -= G3 * HGRU;
    if (idx < G3 * FIN) {
        int j = idx / FIN, k = idx - j * FIN;
        g_wiht[k * G3P + j] = Wih[idx];
        return;
    }
    idx -= G3 * FIN;
    if (idx < G3) { g_bihp[idx] = bih[idx]; return; }
    idx -= G3;
    if (idx < DMLP * HGRU) {
        int c = idx / HGRU, k = idx - c * HGRU;
        g_wmt[0][k * 256 + c] = W1[idx];
        return;
    }
    idx -= DMLP * HGRU;
    if (idx < 4 * DMLP * DMLP) {
        int l = idx / (DMLP * DMLP);
        int r = idx - l * (DMLP * DMLP);
        int c = r / DMLP, k = r - c * DMLP;
        const float* W = (l == 0) ? W2 : (l == 1) ? W3 : (l == 2) ? W4 : W5;
        g_wmt[l + 1][k * 256 + c] = W[r];
        return;
    }
    idx -= 4 * DMLP * DMLP;
    if (idx < 5 * DMLP) {
        int l = idx / DMLP, c = idx - l * DMLP;
        const float* B = (l == 0) ? b1 : (l == 1) ? b2 : (l == 2) ? b3
                        : (l == 3) ? b4 : b5;
        g_bmp[l][c] = B[c];
        return;
    }
    idx -= 5 * DMLP;
    if (idx < DOUT * DMLP) {
        int c = idx / DMLP, k = idx - c * DMLP;
        g_w6t[k * 32 + c] = W6[idx];
        return;
    }
    idx -= DOUT * DMLP;
    if (idx < DOUT) g_b6p[idx] = b6[idx];
}

// ---- gi projection ----
__global__ __launch_bounds__(G3P) void gi_kernel(const float* __restrict__ hist)
{
    __shared__ float2 xs[FIN];
    const int j = threadIdx.x;
    const int r0 = blockIdx.x * 2;

    const float* h0 = hist + ((size_t)r0 * TB + (TB - 1)) * FIN;
    const float* h1 = hist + ((size_t)(r0 + 1) * TB + (TB - 1)) * FIN;
    for (int k = j; k < FIN; k += G3P) xs[k] = make_float2(h0[k], h1[k]);
    __syncthreads();

    float bv = g_bihp[j];
    float a0 = bv, a1 = bv;
#pragma unroll 16
    for (int k = 0; k < FIN; k++) {
        float w = g_wiht[k * G3P + j];
        float2 x = xs[k];
        a0 = fmaf(x.x, w, a0);
        a1 = fmaf(x.y, w, a1);
    }
    if (j < G3) {
        g_gi[r0 * G3 + j]       = a0;
        g_gi[(r0 + 1) * G3 + j] = a1;
    }
}

// ---- fused 6-layer MLP: 512 thr = 64 col-groups x 8-way K-split,
//      explicit 8-load batches so LDGs pipeline ----
__global__ __launch_bounds__(512) void mlp_kernel(float* __restrict__ out)
{
    __shared__ float2 xbuf[256];
    __shared__ float4 red[8][64][2];
    const int tid = threadIdx.x;
    const int cg = tid & 63;        // cols 4cg..4cg+3
    const int ks = tid >> 6;        // K-split 0..7: k in [32ks, 32ks+32)
    const int r0 = blockIdx.x * 2;
    const int kbase = ks * 32;

    if (tid < 256) {
        float2 v = make_float2(0.f, 0.f);
        if (tid < HGRU)
            v = make_float2(g_x[r0 * HP + tid], g_x[(r0 + 1) * HP + tid]);
        xbuf[tid] = v;
    }
    __syncthreads();

#pragma unroll
    for (int l = 0; l < 5; l++) {
        const float4* wt4 = reinterpret_cast<const float4*>(g_wmt[l]);
        float4 a0 = make_float4(0.f, 0.f, 0.f, 0.f);
        float4 a1 = a0;
#pragma unroll
        for (int g = 0; g < 4; g++) {
            float4 wb[8];
            float2 xb[8];
#pragma unroll
            for (int u = 0; u < 8; u++) {      // 8 independent LDG.128 + LDS
                int k = kbase + g * 8 + u;
                wb[u] = wt4[k * 64 + cg];
                xb[u] = xbuf[k];
            }
#pragma unroll
            for (int u = 0; u < 8; u++) {
                a0.x = fmaf(xb[u].x, wb[u].x, a0.x);
                a0.y = fmaf(xb[u].x, wb[u].y, a0.y);
                a0.z = fmaf(xb[u].x, wb[u].z, a0.z);
                a0.w = fmaf(xb[u].x, wb[u].w, a0.w);
                a1.x = fmaf(xb[u].y, wb[u].x, a1.x);
                a1.y = fmaf(xb[u].y, wb[u].y, a1.y);
                a1.z = fmaf(xb[u].y, wb[u].z, a1.z);
                a1.w = fmaf(xb[u].y, wb[u].w, a1.w);
            }
        }
        red[ks][cg][0] = a0;
        red[ks][cg][1] = a1;
        __syncthreads();
        if (ks == 0) {
            float4 s0 = red[0][cg][0], s1 = red[0][cg][1];
#pragma unroll
            for (int q = 1; q < 8; q++) {
                float4 t0 = red[q][cg][0], t1 = red[q][cg][1];
                s0.x += t0.x; s0.y += t0.y; s0.z += t0.z; s0.w += t0.w;
                s1.x += t1.x; s1.y += t1.y; s1.z += t1.z; s1.w += t1.w;
            }
            float4 b = reinterpret_cast<const float4*>(g_bmp[l])[cg];
            xbuf[4 * cg + 0] = make_float2(fmaxf(s0.x + b.x, 0.f), fmaxf(s1.x + b.x, 0.f));
            xbuf[4 * cg + 1] = make_float2(fmaxf(s0.y + b.y, 0.f), fmaxf(s1.y + b.y, 0.f));
            xbuf[4 * cg + 2] = make_float2(fmaxf(s0.z + b.z, 0.f), fmaxf(s1.z + b.z, 0.f));
            xbuf[4 * cg + 3] = make_float2(fmaxf(s0.w + b.w, 0.f), fmaxf(s1.w + b.w, 0.f));
        }
        __syncthreads();
    }

    // layer 6: 17 outputs (weights padded to 32 cols)
    {
        const float4* w6 = reinterpret_cast<const float4*>(g_w6t);
        float4 a0 = make_float4(0.f, 0.f, 0.f, 0.f);
        float4 a1 = a0;
        if (cg < 8) {
#pragma unroll
            for (int g = 0; g < 4; g++) {
                float4 wb[8];
                float2 xb[8];
#pragma unroll
                for (int u = 0; u < 8; u++) {
                    int k = kbase + g * 8 + u;
                    wb[u] = w6[k * 8 + cg];
                    xb[u] = xbuf[k];
                }
#pragma unroll
                for (int u = 0; u < 8; u++) {
                    a0.x = fmaf(xb[u].x, wb[u].x, a0.x);
                    a0.y = fmaf(xb[u].x, wb[u].y, a0.y);
                    a0.z = fmaf(xb[u].x, wb[u].z, a0.z);
                    a0.w = fmaf(xb[u].x, wb[u].w, a0.w);
                    a1.x = fmaf(xb[u].y, wb[u].x, a1.x);
                    a1.y = fmaf(xb[u].y, wb[u].y, a1.y);
                    a1.z = fmaf(xb[u].y, wb[u].z, a1.z);
                    a1.w = fmaf(xb[u].y, wb[u].w, a1.w);
                }
            }
        }
        red[ks][cg][0] = a0;
        red[ks][cg][1] = a1;
        __syncthreads();
        if (ks == 0 && cg < 5) {
            float4 s0 = red[0][cg][0], s1 = red[0][cg][1];
#pragma unroll
            for (int q = 1; q < 8; q++) {
                float4 t0 = red[q][cg][0], t1 = red[q][cg][1];
                s0.x += t0.x; s0.y += t0.y; s0.z += t0.z; s0.w += t0.w;
                s1.x += t1.x; s1.y += t1.y; s1.z += t1.z; s1.w += t1.w;
            }
            float4 b = reinterpret_cast<const float4*>(g_b6p)[cg];
            float o0[4] = {s0.x + b.x, s0.y + b.y, s0.z + b.z, s0.w + b.w};
            float o1[4] = {s1.x + b.x, s1.y + b.y, s1.z + b.z, s1.w + b.w};
#pragma unroll
            for (int i = 0; i < 4; i++) {
                int c = 4 * cg + i;
                if (c < DOUT) {
                    out[r0 * DOUT + c]       = o0[i];
                    out[(r0 + 1) * DOUT + c] = o1[i];
                }
            }
        }
    }
}

// ---- GRU recurrence: 48/18 split + explicit 4-quad load groups ----
__device__ __forceinline__ float fast_sigmoid(float x) {
    return 1.f / (1.f + __expf(-x));
}
__device__ __forceinline__ float fast_tanh(float x) {
    float e = __expf(-2.f * x);
    return (1.f - e) / (1.f + e);
}
__device__ __forceinline__ void fma2(ull& acc, ull h, ull w) {
    asm("fma.rn.f32x2 %0, %1, %2, %0;" : "+l"(acc) : "l"(h), "l"(w));
}

__global__ __launch_bounds__(G3P, 1) void gru_kernel(const float* __restrict__ b_hh)
{
    __shared__ __align__(16) float h_sh[HP];     // 33 quads
    __shared__ float gh_sh[G3];
    __shared__ float gi_sh[G3];
    __shared__ ull tail_w[NTAIL][G3P];

    const int j = threadIdx.x;

    ull w2[NREGP];
    float bj = 0.f;
    if (j < G3) {
        const ull* wr = reinterpret_cast<const ull*>(g_wpad + j * HPW);
#pragma unroll
        for (int i = 0; i < NREGP; i++) w2[i] = wr[i];
#pragma unroll
        for (int t = 0; t < NTAIL; t++) tail_w[t][j] = wr[NREGP + t];
        bj = b_hh[j];
    }
    if (j < HP) h_sh[j] = 0.f;

    float gi_v = (j < G3) ? g_gi[j] : 0.f;
    __syncthreads();

    const ulonglong2* hv2 = reinterpret_cast<const ulonglong2*>(h_sh);

    for (int n = 0; n < NSEQ; n++) {
        float gi_cur = gi_v;
        if (j < G3 && n + 1 < NSEQ) gi_v = __ldg(g_gi + (n + 1) * G3 + j);

        if (j < G3) {
            ull acc0, acc1 = 0ULL;
            asm("mov.b64 %0, {%1, %2};" : "=l"(acc0) : "f"(bj), "f"(0.f));
            // register part: quads 0..23 in 6 groups of 4 (staged loads)
#pragma unroll
            for (int g = 0; g < 6; g++) {
                ulonglong2 h0 = hv2[4 * g + 0];
                ulonglong2 h1 = hv2[4 * g + 1];
                ulonglong2 h2 = hv2[4 * g + 2];
                ulonglong2 h3 = hv2[4 * g + 3];
                fma2(acc0, h0.x, w2[8 * g + 0]); fma2(acc1, h0.y, w2[8 * g + 1]);
                fma2(acc0, h1.x, w2[8 * g + 2]); fma2(acc1, h1.y, w2[8 * g + 3]);
                fma2(acc0, h2.x, w2[8 * g + 4]); fma2(acc1, h2.y, w2[8 * g + 5]);
                fma2(acc0, h3.x, w2[8 * g + 6]); fma2(acc1, h3.y, w2[8 * g + 7]);
            }
            // smem tail: quads 24..32 in 3 groups of 3
#pragma unroll
            for (int t = 0; t < 9; t += 3) {
                ulonglong2 h0 = hv2[24 + t];
                ulonglong2 h1 = hv2[25 + t];
                ulonglong2 h2 = hv2[26 + t];
                ull wa = tail_w[2 * t + 0][j], wb = tail_w[2 * t + 1][j];
                ull wc = tail_w[2 * t + 2][j], wd = tail_w[2 * t + 3][j];
                ull we = tail_w[2 * t + 4][j], wf = tail_w[2 * t + 5][j];
                fma2(acc0, h0.x, wa); fma2(acc1, h0.y, wb);
                fma2(acc0, h1.x, wc); fma2(acc1, h1.y, wd);
                fma2(acc0, h2.x, we); fma2(acc1, h2.y, wf);
            }
            float a0, a1, a2, a3;
            asm("mov.b64 {%0, %1}, %2;" : "=f"(a0), "=f"(a1) : "l"(acc0));
            asm("mov.b64 {%0, %1}, %2;" : "=f"(a2), "=f"(a3) : "l"(acc1));
            gh_sh[j] = (a0 + a2) + (a1 + a3);
            gi_sh[j] = gi_cur;
        }
        __syncthreads();

        if (j < HGRU) {
            float ir = gi_sh[j], iz = gi_sh[j + HGRU], in_ = gi_sh[j + 2 * HGRU];
            float hr = gh_sh[j], hz = gh_sh[j + HGRU], hn = gh_sh[j + 2 * HGRU];
            float r  = fast_sigmoid(ir + hr);
            float z  = fast_sigmoid(iz + hz);
            float nn = fast_tanh(in_ + r * hn);
            float hp = h_sh[j];
            float hnew = nn + z * (hp - nn);
            h_sh[j] = hnew;
            g_x[n * HP + j] = hnew;
        }
        __syncthreads();
    }
}

// ---- dummy: shifts gru_kernel into profiled launch slot #4 ----
__global__ void dummy_kernel() {}

extern "C" void kernel_launch(void* const* d_in, const int* in_sizes, int n_in,
                              void* d_out, int out_size)
{
    const float* history = (const float*)d_in[0];
    const float* W_ih = (const float*)d_in[1];
    const float* W_hh = (const float*)d_in[2];
    const float* b_ih = (const float*)d_in[3];
    const float* b_hh = (const float*)d_in[4];
    const float* W1 = (const float*)d_in[5];  const float* b1 = (const float*)d_in[6];
    const float* W2 = (const float*)d_in[7];  const float* b2 = (const float*)d_in[8];
    const float* W3 = (const float*)d_in[9];  const float* b3 = (const float*)d_in[10];
    const float* W4 = (const float*)d_in[11]; const float* b4 = (const float*)d_in[12];
    const float* W5 = (const float*)d_in[13]; const float* b5 = (const float*)d_in[14];
    const float* W6 = (const float*)d_in[15]; const float* b6 = (const float*)d_in[16];
    float* out = (float*)d_out;

    const int prep_total = G3 * HGRU + G3 * FIN + G3 + DMLP * HGRU
                         + 4 * DMLP * DMLP + 5 * DMLP + DOUT * DMLP + DOUT;

    dummy_kernel<<<1, 32>>>();                                      // launch 1
    prep_kernel<<<(prep_total + 511) / 512, 512>>>(                 // launch 2
        W_hh, W_ih, b_ih, W1, b1, W2, b2, W3, b3, W4, b4, W5, b5, W6, b6);
    gi_kernel<<<NSEQ / 2, G3P>>>(history);                          // launch 3
    gru_kernel<<<1, G3P>>>(b_hh);                                   // launch 4 (profiled)
    mlp_kernel<<<NSEQ / 2, 512>>>(out);                             // launch 5
}